// round 16
// baseline (speedup 1.0000x reference)
#include <cuda_runtime.h>
#include <cuda_bf16.h>
#include <cstdint>

#define N_X   4096
#define M_SV  8192
#define D_DIM 512

#define TILE_M   128
#define TILE_N   128
#define N_CHUNKS 8                   // K chunks of 64
#define NPART    (M_SV / TILE_N)     // 64

// ---- scratch in device globals (no allocation allowed) ----
__device__ __nv_bfloat16 g_Xb[N_X * D_DIM];
__device__ __nv_bfloat16 g_SVb[M_SV * D_DIM];
__device__ float g_fx[N_X];              // exp(-gamma * ||x_n||^2)
__device__ float g_w[M_SV];              // DC[m] * exp(-gamma * ||sv_m||^2)
__device__ float g_part[NPART * N_X];    // split-N partials (deterministic)

// ---- dynamic smem layout (relative to 1024B-aligned base) ----
#define STAGE_BYTES 32768      // A tile 16KB + B tile 16KB
#define OFF_BSTAGE  16384
#define NSTAGES     3
#define OFF_W       98304      // 128 floats (512B)
#define OFF_RED     98816      // 256 floats (1KB)
#define SMEM_BYTES  (99840 + 1024)   // x2 CTAs = ~202KB/SM

// ============================ helpers ============================
__device__ __forceinline__ uint32_t smem_u32(const void* p) {
    uint32_t a;
    asm("{ .reg .u64 t; cvta.to.shared.u64 t, %1; cvt.u32.u64 %0, t; }" : "=r"(a) : "l"(p));
    return a;
}
__device__ __forceinline__ float ex2f(float x) {
    float y; asm("ex2.approx.ftz.f32 %0, %1;" : "=f"(y) : "f"(x)); return y;
}
__device__ __forceinline__ uint32_t pack_bf2(float lo, float hi) {
    __nv_bfloat162 b = __floats2bfloat162_rn(lo, hi);
    return *reinterpret_cast<uint32_t*>(&b);
}
__device__ __forceinline__ void cpasync16(uint32_t dst, const void* src) {
    asm volatile("cp.async.cg.shared.global [%0], [%1], 16;" :: "r"(dst), "l"(src) : "memory");
}
#define CP_COMMIT() asm volatile("cp.async.commit_group;" ::: "memory")
#define CP_WAIT(n)  asm volatile("cp.async.wait_group %0;" :: "n"(n) : "memory")

__device__ __forceinline__ void ldsm4(uint32_t* r, uint32_t addr) {
    asm volatile("ldmatrix.sync.aligned.m8n8.x4.shared.b16 {%0,%1,%2,%3}, [%4];"
                 : "=r"(r[0]), "=r"(r[1]), "=r"(r[2]), "=r"(r[3]) : "r"(addr));
}
__device__ __forceinline__ void mma16816(float* c, const uint32_t* a, uint32_t b0, uint32_t b1) {
    asm volatile("mma.sync.aligned.m16n8k16.row.col.f32.bf16.bf16.f32 "
                 "{%0,%1,%2,%3}, {%4,%5,%6,%7}, {%8,%9}, {%0,%1,%2,%3};"
                 : "+f"(c[0]), "+f"(c[1]), "+f"(c[2]), "+f"(c[3])
                 : "r"(a[0]), "r"(a[1]), "r"(a[2]), "r"(a[3]), "r"(b0), "r"(b1));
}
__device__ __forceinline__ uint32_t sw128(uint32_t off) { return off ^ ((off >> 3) & 0x70); }

// ============================ prep kernel ============================
// One warp per TWO rows. Each lane loads 4 CONSECUTIVE float4 (64B contiguous,
// MLP=8 across the two rows) and writes two fully-coalesced 16B uint4 stores
// of packed bf16. Shuffle-only reduction for ||row||^2 -> fx/w.
__global__ __launch_bounds__(256)
void prep_kernel(const float* __restrict__ X, const float* __restrict__ SV,
                 const float* __restrict__ DC, const float* __restrict__ gammaPtr) {
    int warp = (blockIdx.x * 256 + threadIdx.x) >> 5;   // 0 .. 6143
    int lane = threadIdx.x & 31;
    float g = gammaPtr[0];

    int r0 = warp * 2;
    int r1 = warp * 2 + 1;

    auto rowptr_src = [&](int r) -> const float* {
        return (r < N_X) ? (X + (size_t)r * D_DIM) : (SV + (size_t)(r - N_X) * D_DIM);
    };
    auto rowptr_dst = [&](int r) -> __nv_bfloat16* {
        return (r < N_X) ? (g_Xb + (size_t)r * D_DIM) : (g_SVb + (size_t)(r - N_X) * D_DIM);
    };

    const float4* s0 = reinterpret_cast<const float4*>(rowptr_src(r0));
    const float4* s1 = reinterpret_cast<const float4*>(rowptr_src(r1));
    float4 v0[4], v1[4];
    #pragma unroll
    for (int i = 0; i < 4; ++i) v0[i] = s0[lane * 4 + i];   // 64B contiguous per lane
    #pragma unroll
    for (int i = 0; i < 4; ++i) v1[i] = s1[lane * 4 + i];

    float ss0 = 0.0f, ss1 = 0.0f;
    uint32_t p0[8], p1[8];
    #pragma unroll
    for (int i = 0; i < 4; ++i) {
        ss0 += v0[i].x * v0[i].x + v0[i].y * v0[i].y + v0[i].z * v0[i].z + v0[i].w * v0[i].w;
        p0[2 * i + 0] = pack_bf2(v0[i].x, v0[i].y);
        p0[2 * i + 1] = pack_bf2(v0[i].z, v0[i].w);
        ss1 += v1[i].x * v1[i].x + v1[i].y * v1[i].y + v1[i].z * v1[i].z + v1[i].w * v1[i].w;
        p1[2 * i + 0] = pack_bf2(v1[i].x, v1[i].y);
        p1[2 * i + 1] = pack_bf2(v1[i].z, v1[i].w);
    }

    uint4* d0 = reinterpret_cast<uint4*>(rowptr_dst(r0));
    uint4* d1 = reinterpret_cast<uint4*>(rowptr_dst(r1));
    d0[lane * 2 + 0] = make_uint4(p0[0], p0[1], p0[2], p0[3]);
    d0[lane * 2 + 1] = make_uint4(p0[4], p0[5], p0[6], p0[7]);
    d1[lane * 2 + 0] = make_uint4(p1[0], p1[1], p1[2], p1[3]);
    d1[lane * 2 + 1] = make_uint4(p1[4], p1[5], p1[6], p1[7]);

    #pragma unroll
    for (int o = 16; o > 0; o >>= 1) {
        ss0 += __shfl_xor_sync(0xFFFFFFFFu, ss0, o);
        ss1 += __shfl_xor_sync(0xFFFFFFFFu, ss1, o);
    }
    if (lane == 0) {
        float e0 = __expf(-g * ss0);
        if (r0 < N_X) g_fx[r0] = e0; else g_w[r0 - N_X] = DC[r0 - N_X] * e0;
        float e1 = __expf(-g * ss1);
        if (r1 < N_X) g_fx[r1] = e1; else g_w[r1 - N_X] = DC[r1 - N_X] * e1;
    }
}

// ============================ main GEMM+epilogue ============================
// Grid (32, 64): blockIdx.x -> M tile (128 X rows), blockIdx.y -> N tile (128 SVs).
// 128 threads = 4 warps as 2 (M) x 2 (N); WARP TILE 64x64 (128 acc regs).
// 3-stage cp.async ring, one __syncthreads per chunk, 2 CTAs/SM.  (R9 mainloop.)
__global__ __launch_bounds__(128, 2)
void rbf_main(const float* __restrict__ gammaPtr) {
    extern __shared__ char smem_raw[];
    char* smb = (char*)((((uintptr_t)smem_raw) + 1023) & ~(uintptr_t)1023);
    uint32_t sb = (smem_u32(smem_raw) + 1023u) & ~1023u;

    const int tid  = threadIdx.x;
    const int lane = tid & 31;
    const int wid  = tid >> 5;
    const int warpM = wid & 1;   // 0..1  (64-row half)
    const int warpN = wid >> 1;  // 0..1  (64-col half)
    const int m0 = blockIdx.x * TILE_M;
    const int n0 = blockIdx.y * TILE_N;

    reinterpret_cast<float*>(smb + OFF_W)[tid] = g_w[n0 + tid];

    const uint4* X4  = reinterpret_cast<const uint4*>(g_Xb);   // 64 x 16B per row
    const uint4* SV4 = reinterpret_cast<const uint4*>(g_SVb);

    // ---- async stage loader: 8 A + 8 B 16B-transfers per thread ----
    auto issue_load = [&](int stage, int ks) {
        uint32_t sA = sb + stage * STAGE_BYTES;
        uint32_t sB = sA + OFF_BSTAGE;
        #pragma unroll
        for (int i = 0; i < 8; ++i) {
            int q = tid + i * 128;           // 0..1023  (128 rows x 8 chunks)
            int row = q >> 3, c = q & 7;
            cpasync16(sA + sw128(row * 128 + c * 16),
                      &X4[(size_t)(m0 + row) * 64 + ks * 8 + c]);
        }
        #pragma unroll
        for (int i = 0; i < 8; ++i) {
            int q = tid + i * 128;
            int row = q >> 3, c = q & 7;
            cpasync16(sB + sw128(row * 128 + c * 16),
                      &SV4[(size_t)(n0 + row) * 64 + ks * 8 + c]);
        }
        CP_COMMIT();
    };

    float acc[4][8][4];
    #pragma unroll
    for (int a = 0; a < 4; ++a)
        #pragma unroll
        for (int b = 0; b < 8; ++b)
            #pragma unroll
            for (int c = 0; c < 4; ++c) acc[a][b][c] = 0.0f;

    issue_load(0, 0);
    issue_load(1, 1);

    // per-lane fragment address pieces
    const int arow0 = warpM * 64 + (lane & 15);          // + mf*16
    const uint32_t acb = ((lane >> 4) & 1) * 16;
    const int brow0 = warpN * 64 + ((lane & 16) >> 1) + (lane & 7);   // + p*16
    const uint32_t bcb = ((lane >> 3) & 1) * 16;

    #pragma unroll 1
    for (int ks = 0; ks < N_CHUNKS; ++ks) {
        if (ks < N_CHUNKS - 1) CP_WAIT(1); else CP_WAIT(0);
        __syncthreads();                       // stage ks ready; stage (ks+2)%3 free
        if (ks + 2 < N_CHUNKS) issue_load((ks + 2) % NSTAGES, ks + 2);

        uint32_t sA = sb + (ks % NSTAGES) * STAGE_BYTES;
        uint32_t sB = sA + OFF_BSTAGE;

        #pragma unroll
        for (int kstep = 0; kstep < 4; ++kstep) {
            uint32_t kc = (uint32_t)kstep * 32;
            uint32_t a[4][4];
            #pragma unroll
            for (int mf = 0; mf < 4; ++mf) {
                int row = arow0 + mf * 16;
                uint32_t addr = sA + row * 128 + ((kc + acb) ^ ((row & 7) << 4));
                ldsm4(a[mf], addr);
            }
            uint32_t b[4][4];
            #pragma unroll
            for (int p = 0; p < 4; ++p) {
                int row = brow0 + p * 16;
                uint32_t addr = sB + row * 128 + ((kc + bcb) ^ ((row & 7) << 4));
                ldsm4(b[p], addr);
            }
            #pragma unroll
            for (int mf = 0; mf < 4; ++mf)
                #pragma unroll
                for (int p = 0; p < 4; ++p) {
                    mma16816(acc[mf][2 * p + 0], a[mf], b[p][0], b[p][1]);
                    mma16816(acc[mf][2 * p + 1], a[mf], b[p][2], b[p][3]);
                }
        }
    }

    // ---- epilogue: sum_n w[n] * exp2(c2 * cross) per output row ----
    float c2 = 2.0f * gammaPtr[0] * 1.44269504f;
    const float2* wt = reinterpret_cast<const float2*>(smb + OFF_W);
    float2 wv[8];
    #pragma unroll
    for (int nf = 0; nf < 8; ++nf)
        wv[nf] = wt[warpN * 32 + nf * 4 + (lane & 3)];

    float rsum[4][2];
    #pragma unroll
    for (int mf = 0; mf < 4; ++mf) { rsum[mf][0] = 0.0f; rsum[mf][1] = 0.0f; }
    #pragma unroll
    for (int mf = 0; mf < 4; ++mf)
        #pragma unroll
        for (int nf = 0; nf < 8; ++nf) {
            rsum[mf][0] = fmaf(wv[nf].x, ex2f(acc[mf][nf][0] * c2), rsum[mf][0]);
            rsum[mf][0] = fmaf(wv[nf].y, ex2f(acc[mf][nf][1] * c2), rsum[mf][0]);
            rsum[mf][1] = fmaf(wv[nf].x, ex2f(acc[mf][nf][2] * c2), rsum[mf][1]);
            rsum[mf][1] = fmaf(wv[nf].y, ex2f(acc[mf][nf][3] * c2), rsum[mf][1]);
        }

    float* red = reinterpret_cast<float*>(smb + OFF_RED);   // [2 warpN][128 rows]
    #pragma unroll
    for (int mf = 0; mf < 4; ++mf)
        #pragma unroll
        for (int h = 0; h < 2; ++h) {
            float v = rsum[mf][h];
            v += __shfl_xor_sync(0xFFFFFFFFu, v, 1);
            v += __shfl_xor_sync(0xFFFFFFFFu, v, 2);
            if ((lane & 3) == 0) {
                int rowLocal = warpM * 64 + mf * 16 + h * 8 + (lane >> 2);
                red[warpN * 128 + rowLocal] = v;
            }
        }
    __syncthreads();
    g_part[(size_t)blockIdx.y * N_X + m0 + tid] = red[tid] + red[128 + tid];
}

// ============================ final reduce ============================
__global__ void reduce_kernel(const float* __restrict__ IC, float* __restrict__ out) {
    int i = blockIdx.x * 256 + threadIdx.x;
    float s = 0.0f;
    #pragma unroll
    for (int j = 0; j < NPART; ++j) s += g_part[(size_t)j * N_X + i];
    out[i] = fmaf(g_fx[i], s, IC[0]);
}

// ============================ launch ============================
extern "C" void kernel_launch(void* const* d_in, const int* in_sizes, int n_in,
                              void* d_out, int out_size) {
    (void)in_sizes; (void)n_in; (void)out_size;
    const float* X     = (const float*)d_in[0];
    const float* SV    = (const float*)d_in[1];
    const float* DC    = (const float*)d_in[2];
    const float* IC    = (const float*)d_in[3];
    const float* gamma = (const float*)d_in[4];
    float* out = (float*)d_out;

    cudaFuncSetAttribute(rbf_main, cudaFuncAttributeMaxDynamicSharedMemorySize, SMEM_BYTES);

    prep_kernel<<<(N_X + M_SV) / 16, 256>>>(X, SV, DC, gamma);
    rbf_main<<<dim3(N_X / TILE_M, M_SV / TILE_N), 128, SMEM_BYTES>>>(gamma);
    reduce_kernel<<<N_X / 256, 256>>>(IC, out);
}

// round 17
// speedup vs baseline: 1.0392x; 1.0392x over previous
#include <cuda_runtime.h>
#include <cuda_bf16.h>
#include <cstdint>

#define N_X   4096
#define M_SV  8192
#define D_DIM 512

#define TILE_M   128
#define TILE_N   128
#define N_CHUNKS 8                   // K chunks of 64
#define NPART    (M_SV / TILE_N)     // 64

// ---- scratch in device globals (no allocation allowed) ----
__device__ __nv_bfloat16 g_Xb[N_X * D_DIM];
__device__ __nv_bfloat16 g_SVb[M_SV * D_DIM];
__device__ float g_fx[N_X];              // exp(-gamma * ||x_n||^2)
__device__ float g_w[M_SV];              // DC[m] * exp(-gamma * ||sv_m||^2)
__device__ float g_part[NPART * N_X];    // split-N partials (deterministic)

// ---- dynamic smem layout (relative to 1024B-aligned base) ----
#define STAGE_BYTES 32768      // A tile 16KB + B tile 16KB
#define OFF_BSTAGE  16384
#define NSTAGES     3
#define OFF_W       98304      // 128 floats (512B)
#define OFF_RED     98816      // 256 floats (1KB)
#define SMEM_BYTES  (99840 + 1024)   // x2 CTAs = ~202KB/SM

// ============================ helpers ============================
__device__ __forceinline__ uint32_t smem_u32(const void* p) {
    uint32_t a;
    asm("{ .reg .u64 t; cvta.to.shared.u64 t, %1; cvt.u32.u64 %0, t; }" : "=r"(a) : "l"(p));
    return a;
}
__device__ __forceinline__ float ex2f(float x) {
    float y; asm("ex2.approx.ftz.f32 %0, %1;" : "=f"(y) : "f"(x)); return y;
}
__device__ __forceinline__ uint32_t pack_bf2(float lo, float hi) {
    __nv_bfloat162 b = __floats2bfloat162_rn(lo, hi);
    return *reinterpret_cast<uint32_t*>(&b);
}
__device__ __forceinline__ void cpasync16(uint32_t dst, const void* src) {
    asm volatile("cp.async.cg.shared.global [%0], [%1], 16;" :: "r"(dst), "l"(src) : "memory");
}
#define CP_COMMIT() asm volatile("cp.async.commit_group;" ::: "memory")
#define CP_WAIT(n)  asm volatile("cp.async.wait_group %0;" :: "n"(n) : "memory")

__device__ __forceinline__ void ldsm4(uint32_t* r, uint32_t addr) {
    asm volatile("ldmatrix.sync.aligned.m8n8.x4.shared.b16 {%0,%1,%2,%3}, [%4];"
                 : "=r"(r[0]), "=r"(r[1]), "=r"(r[2]), "=r"(r[3]) : "r"(addr));
}
__device__ __forceinline__ void mma16816(float* c, const uint32_t* a, uint32_t b0, uint32_t b1) {
    asm volatile("mma.sync.aligned.m16n8k16.row.col.f32.bf16.bf16.f32 "
                 "{%0,%1,%2,%3}, {%4,%5,%6,%7}, {%8,%9}, {%0,%1,%2,%3};"
                 : "+f"(c[0]), "+f"(c[1]), "+f"(c[2]), "+f"(c[3])
                 : "r"(a[0]), "r"(a[1]), "r"(a[2]), "r"(a[3]), "r"(b0), "r"(b1));
}
__device__ __forceinline__ uint32_t sw128(uint32_t off) { return off ^ ((off >> 3) & 0x70); }

// ============================ prep kernel ============================
// One warp per TWO rows (MLP=8): R9's fully-coalesced interleaved loads
// (lane + i*32), with the two adjacent 4B bf16x2 stores merged into one
// 8B uint2 store per (row, i). Shuffle-only reduction -> fx/w.
__global__ __launch_bounds__(256)
void prep_kernel(const float* __restrict__ X, const float* __restrict__ SV,
                 const float* __restrict__ DC, const float* __restrict__ gammaPtr) {
    int warp = (blockIdx.x * 256 + threadIdx.x) >> 5;   // 0 .. 6143
    int lane = threadIdx.x & 31;
    float g = gammaPtr[0];

    int r0 = warp * 2;
    int r1 = warp * 2 + 1;

    auto rowptr_src = [&](int r) -> const float* {
        return (r < N_X) ? (X + (size_t)r * D_DIM) : (SV + (size_t)(r - N_X) * D_DIM);
    };
    auto rowptr_dst = [&](int r) -> __nv_bfloat16* {
        return (r < N_X) ? (g_Xb + (size_t)r * D_DIM) : (g_SVb + (size_t)(r - N_X) * D_DIM);
    };

    const float4* s0 = reinterpret_cast<const float4*>(rowptr_src(r0));
    const float4* s1 = reinterpret_cast<const float4*>(rowptr_src(r1));
    float4 v0[4], v1[4];
    #pragma unroll
    for (int i = 0; i < 4; ++i) v0[i] = s0[lane + i * 32];   // coalesced per instruction
    #pragma unroll
    for (int i = 0; i < 4; ++i) v1[i] = s1[lane + i * 32];

    float ss0 = 0.0f, ss1 = 0.0f;
    uint2* d0 = reinterpret_cast<uint2*>(rowptr_dst(r0));    // 8B granules (4 bf16)
    uint2* d1 = reinterpret_cast<uint2*>(rowptr_dst(r1));
    #pragma unroll
    for (int i = 0; i < 4; ++i) {
        ss0 += v0[i].x * v0[i].x + v0[i].y * v0[i].y + v0[i].z * v0[i].z + v0[i].w * v0[i].w;
        d0[lane + i * 32] = make_uint2(pack_bf2(v0[i].x, v0[i].y), pack_bf2(v0[i].z, v0[i].w));
        ss1 += v1[i].x * v1[i].x + v1[i].y * v1[i].y + v1[i].z * v1[i].z + v1[i].w * v1[i].w;
        d1[lane + i * 32] = make_uint2(pack_bf2(v1[i].x, v1[i].y), pack_bf2(v1[i].z, v1[i].w));
    }
    #pragma unroll
    for (int o = 16; o > 0; o >>= 1) {
        ss0 += __shfl_xor_sync(0xFFFFFFFFu, ss0, o);
        ss1 += __shfl_xor_sync(0xFFFFFFFFu, ss1, o);
    }
    if (lane == 0) {
        float e0 = __expf(-g * ss0);
        if (r0 < N_X) g_fx[r0] = e0; else g_w[r0 - N_X] = DC[r0 - N_X] * e0;
        float e1 = __expf(-g * ss1);
        if (r1 < N_X) g_fx[r1] = e1; else g_w[r1 - N_X] = DC[r1 - N_X] * e1;
    }
}

// ============================ main GEMM+epilogue ============================
// Grid (32, 64): blockIdx.x -> M tile (128 X rows), blockIdx.y -> N tile (128 SVs).
// 128 threads = 4 warps as 2 (M) x 2 (N); WARP TILE 64x64 (128 acc regs).
// 3-stage cp.async ring, one __syncthreads per chunk, 2 CTAs/SM.  (R9 mainloop.)
__global__ __launch_bounds__(128, 2)
void rbf_main(const float* __restrict__ gammaPtr) {
    extern __shared__ char smem_raw[];
    char* smb = (char*)((((uintptr_t)smem_raw) + 1023) & ~(uintptr_t)1023);
    uint32_t sb = (smem_u32(smem_raw) + 1023u) & ~1023u;

    const int tid  = threadIdx.x;
    const int lane = tid & 31;
    const int wid  = tid >> 5;
    const int warpM = wid & 1;   // 0..1  (64-row half)
    const int warpN = wid >> 1;  // 0..1  (64-col half)
    const int m0 = blockIdx.x * TILE_M;
    const int n0 = blockIdx.y * TILE_N;

    reinterpret_cast<float*>(smb + OFF_W)[tid] = g_w[n0 + tid];

    const uint4* X4  = reinterpret_cast<const uint4*>(g_Xb);   // 64 x 16B per row
    const uint4* SV4 = reinterpret_cast<const uint4*>(g_SVb);

    // ---- async stage loader: 8 A + 8 B 16B-transfers per thread ----
    auto issue_load = [&](int stage, int ks) {
        uint32_t sA = sb + stage * STAGE_BYTES;
        uint32_t sB = sA + OFF_BSTAGE;
        #pragma unroll
        for (int i = 0; i < 8; ++i) {
            int q = tid + i * 128;           // 0..1023  (128 rows x 8 chunks)
            int row = q >> 3, c = q & 7;
            cpasync16(sA + sw128(row * 128 + c * 16),
                      &X4[(size_t)(m0 + row) * 64 + ks * 8 + c]);
        }
        #pragma unroll
        for (int i = 0; i < 8; ++i) {
            int q = tid + i * 128;
            int row = q >> 3, c = q & 7;
            cpasync16(sB + sw128(row * 128 + c * 16),
                      &SV4[(size_t)(n0 + row) * 64 + ks * 8 + c]);
        }
        CP_COMMIT();
    };

    float acc[4][8][4];
    #pragma unroll
    for (int a = 0; a < 4; ++a)
        #pragma unroll
        for (int b = 0; b < 8; ++b)
            #pragma unroll
            for (int c = 0; c < 4; ++c) acc[a][b][c] = 0.0f;

    issue_load(0, 0);
    issue_load(1, 1);

    // per-lane fragment address pieces
    const int arow0 = warpM * 64 + (lane & 15);          // + mf*16
    const uint32_t acb = ((lane >> 4) & 1) * 16;
    const int brow0 = warpN * 64 + ((lane & 16) >> 1) + (lane & 7);   // + p*16
    const uint32_t bcb = ((lane >> 3) & 1) * 16;

    #pragma unroll 1
    for (int ks = 0; ks < N_CHUNKS; ++ks) {
        if (ks < N_CHUNKS - 1) CP_WAIT(1); else CP_WAIT(0);
        __syncthreads();                       // stage ks ready; stage (ks+2)%3 free
        if (ks + 2 < N_CHUNKS) issue_load((ks + 2) % NSTAGES, ks + 2);

        uint32_t sA = sb + (ks % NSTAGES) * STAGE_BYTES;
        uint32_t sB = sA + OFF_BSTAGE;

        #pragma unroll
        for (int kstep = 0; kstep < 4; ++kstep) {
            uint32_t kc = (uint32_t)kstep * 32;
            uint32_t a[4][4];
            #pragma unroll
            for (int mf = 0; mf < 4; ++mf) {
                int row = arow0 + mf * 16;
                uint32_t addr = sA + row * 128 + ((kc + acb) ^ ((row & 7) << 4));
                ldsm4(a[mf], addr);
            }
            uint32_t b[4][4];
            #pragma unroll
            for (int p = 0; p < 4; ++p) {
                int row = brow0 + p * 16;
                uint32_t addr = sB + row * 128 + ((kc + bcb) ^ ((row & 7) << 4));
                ldsm4(b[p], addr);
            }
            #pragma unroll
            for (int mf = 0; mf < 4; ++mf)
                #pragma unroll
                for (int p = 0; p < 4; ++p) {
                    mma16816(acc[mf][2 * p + 0], a[mf], b[p][0], b[p][1]);
                    mma16816(acc[mf][2 * p + 1], a[mf], b[p][2], b[p][3]);
                }
        }
    }

    // ---- epilogue: sum_n w[n] * exp2(c2 * cross) per output row ----
    float c2 = 2.0f * gammaPtr[0] * 1.44269504f;
    const float2* wt = reinterpret_cast<const float2*>(smb + OFF_W);
    float2 wv[8];
    #pragma unroll
    for (int nf = 0; nf < 8; ++nf)
        wv[nf] = wt[warpN * 32 + nf * 4 + (lane & 3)];

    float rsum[4][2];
    #pragma unroll
    for (int mf = 0; mf < 4; ++mf) { rsum[mf][0] = 0.0f; rsum[mf][1] = 0.0f; }
    #pragma unroll
    for (int mf = 0; mf < 4; ++mf)
        #pragma unroll
        for (int nf = 0; nf < 8; ++nf) {
            rsum[mf][0] = fmaf(wv[nf].x, ex2f(acc[mf][nf][0] * c2), rsum[mf][0]);
            rsum[mf][0] = fmaf(wv[nf].y, ex2f(acc[mf][nf][1] * c2), rsum[mf][0]);
            rsum[mf][1] = fmaf(wv[nf].x, ex2f(acc[mf][nf][2] * c2), rsum[mf][1]);
            rsum[mf][1] = fmaf(wv[nf].y, ex2f(acc[mf][nf][3] * c2), rsum[mf][1]);
        }

    float* red = reinterpret_cast<float*>(smb + OFF_RED);   // [2 warpN][128 rows]
    #pragma unroll
    for (int mf = 0; mf < 4; ++mf)
        #pragma unroll
        for (int h = 0; h < 2; ++h) {
            float v = rsum[mf][h];
            v += __shfl_xor_sync(0xFFFFFFFFu, v, 1);
            v += __shfl_xor_sync(0xFFFFFFFFu, v, 2);
            if ((lane & 3) == 0) {
                int rowLocal = warpM * 64 + mf * 16 + h * 8 + (lane >> 2);
                red[warpN * 128 + rowLocal] = v;
            }
        }
    __syncthreads();
    g_part[(size_t)blockIdx.y * N_X + m0 + tid] = red[tid] + red[128 + tid];
}

// ============================ final reduce ============================
__global__ void reduce_kernel(const float* __restrict__ IC, float* __restrict__ out) {
    int i = blockIdx.x * 256 + threadIdx.x;
    float s = 0.0f;
    #pragma unroll
    for (int j = 0; j < NPART; ++j) s += g_part[(size_t)j * N_X + i];
    out[i] = fmaf(g_fx[i], s, IC[0]);
}

// ============================ launch ============================
extern "C" void kernel_launch(void* const* d_in, const int* in_sizes, int n_in,
                              void* d_out, int out_size) {
    (void)in_sizes; (void)n_in; (void)out_size;
    const float* X     = (const float*)d_in[0];
    const float* SV    = (const float*)d_in[1];
    const float* DC    = (const float*)d_in[2];
    const float* IC    = (const float*)d_in[3];
    const float* gamma = (const float*)d_in[4];
    float* out = (float*)d_out;

    cudaFuncSetAttribute(rbf_main, cudaFuncAttributeMaxDynamicSharedMemorySize, SMEM_BYTES);

    prep_kernel<<<(N_X + M_SV) / 16, 256>>>(X, SV, DC, gamma);
    rbf_main<<<dim3(N_X / TILE_M, M_SV / TILE_N), 128, SMEM_BYTES>>>(gamma);
    reduce_kernel<<<N_X / 256, 256>>>(IC, out);
}